// round 7
// baseline (speedup 1.0000x reference)
#include <cuda_runtime.h>
#include <cfloat>

// PoolingLayer: out[p, f] = max_k features[neighbor_indices[p, k], f]
// N=100000, NP=50000, K=32, F=128
// Inputs: points (N,3) f32 [unused], features (N,128) f32,
//         neighbor_indices (NP,32) int32. Output (NP,128) f32.
// L2-bandwidth-bound random gather. Feature table (51MB) is L2-resident;
// keep streaming data (idx, out) from evicting it, and keep 8 rows in
// flight per warp to saturate the L1tex/L2 queues.

#define NPTS   100000
#define NP_OUT 50000
#define KNBR   32
#define FDIM   128            // 512 bytes per feature row

__device__ __forceinline__ float4 fmax4(float4 a, float4 b) {
    a.x = fmaxf(a.x, b.x);
    a.y = fmaxf(a.y, b.y);
    a.z = fmaxf(a.z, b.z);
    a.w = fmaxf(a.w, b.w);
    return a;
}

__global__ __launch_bounds__(256)
void pool_max_kernel(const char* __restrict__ feats_b,   // features base (bytes)
                     const int* __restrict__ nbr,        // (NP, 32) int32
                     float4* __restrict__ out)            // (NP, 32) float4
{
    const int gtid = blockIdx.x * blockDim.x + threadIdx.x;
    const int warp = gtid >> 5;          // one warp per output point
    const int lane = gtid & 31;          // one float4 column per lane
    if (warp >= NP_OUT) return;

    // Coalesced, streaming load of this point's 32 neighbor indices
    // (single-use data: don't let it pollute L2).
    int my_idx = __ldcs(nbr + (size_t)warp * KNBR + lane);
    my_idx = min(max(my_idx, 0), NPTS - 1);        // safety clamp (no-op on valid data)
    const int my_off = my_idx << 9;                // row byte offset (*512)

    const char* base = feats_b + (lane << 4);      // fold lane column offset in once

    const float4 NEG = make_float4(-FLT_MAX, -FLT_MAX, -FLT_MAX, -FLT_MAX);
    float4 acc0 = NEG, acc1 = NEG, acc2 = NEG, acc3 = NEG;

    // 32 neighbors: 8 loads in flight per batch, 4 independent max chains.
    #pragma unroll
    for (int k = 0; k < KNBR; k += 8) {
        const int o0 = __shfl_sync(0xffffffffu, my_off, k + 0);
        const int o1 = __shfl_sync(0xffffffffu, my_off, k + 1);
        const int o2 = __shfl_sync(0xffffffffu, my_off, k + 2);
        const int o3 = __shfl_sync(0xffffffffu, my_off, k + 3);
        const int o4 = __shfl_sync(0xffffffffu, my_off, k + 4);
        const int o5 = __shfl_sync(0xffffffffu, my_off, k + 5);
        const int o6 = __shfl_sync(0xffffffffu, my_off, k + 6);
        const int o7 = __shfl_sync(0xffffffffu, my_off, k + 7);
        float4 v0 = *reinterpret_cast<const float4*>(base + o0);
        float4 v1 = *reinterpret_cast<const float4*>(base + o1);
        float4 v2 = *reinterpret_cast<const float4*>(base + o2);
        float4 v3 = *reinterpret_cast<const float4*>(base + o3);
        float4 v4 = *reinterpret_cast<const float4*>(base + o4);
        float4 v5 = *reinterpret_cast<const float4*>(base + o5);
        float4 v6 = *reinterpret_cast<const float4*>(base + o6);
        float4 v7 = *reinterpret_cast<const float4*>(base + o7);
        acc0 = fmax4(acc0, fmax4(v0, v4));
        acc1 = fmax4(acc1, fmax4(v1, v5));
        acc2 = fmax4(acc2, fmax4(v2, v6));
        acc3 = fmax4(acc3, fmax4(v3, v7));
    }

    acc0 = fmax4(acc0, acc1);
    acc2 = fmax4(acc2, acc3);
    acc0 = fmax4(acc0, acc2);

    // Streaming store: output is single-use, keep it out of the way of the
    // L2-resident feature table.
    __stcs(out + (size_t)warp * (FDIM / 4) + lane, acc0);
}

extern "C" void kernel_launch(void* const* d_in, const int* in_sizes, int n_in,
                              void* d_out, int out_size) {
    // d_in[0] = points (unused), d_in[1] = features, d_in[2] = neighbor_indices
    const char* feats = (const char*)d_in[1];
    const int* nbr = (const int*)d_in[2];
    float4* out = (float4*)d_out;

    const int total_threads = NP_OUT * 32;      // one warp per output point
    const int block = 256;
    const int grid = (total_threads + block - 1) / block;
    pool_max_kernel<<<grid, block>>>(feats, nbr, out);
}